// round 1
// baseline (speedup 1.0000x reference)
#include <cuda_runtime.h>
#include <cstdint>
#include <math.h>

#define N_NODES  50000
#define N_HEDGES 50000
#define NNZ      800000
#define F_IN     256
#define HID      256
#define F_OUT    128

// ---------------- scratch (device globals; no allocs allowed) ----------------
__device__ __align__(128) float g_bufA[N_NODES * HID];
__device__ __align__(128) float g_bufB[N_NODES * HID];
__device__ __align__(128) float g_bufC[N_NODES * HID];
__device__ __align__(128) float g_inv_v[N_NODES];
__device__ __align__(128) float g_inv_e[N_HEDGES];
__device__ __align__(128) int   g_cnt_v[N_NODES];
__device__ __align__(128) int   g_cnt_e[N_HEDGES];
__device__ __align__(128) int   g_vi[NNZ];
__device__ __align__(128) int   g_hi[NNZ];
__device__ int g_flag[1];

// ---------------- small utility kernels ----------------
__global__ void k_zero(float4* p, int n4) {
    int i = blockIdx.x * blockDim.x + threadIdx.x;
    if (i < n4) p[i] = make_float4(0.f, 0.f, 0.f, 0.f);
}

// Detect whether edge_index is int64 (odd 32-bit words of nonneg <2^31 values are 0)
__global__ void k_detect(const int* __restrict__ ei) {
    if (blockIdx.x == 0 && threadIdx.x == 0) {
        int z = 0;
        #pragma unroll
        for (int i = 1; i < 64; i += 2) z |= ei[i];
        g_flag[0] = (z == 0) ? 1 : 0;
    }
}

// Convert edge_index to int32 vi/hi and count degrees
__global__ void k_convert(const void* __restrict__ ei_raw) {
    int i = blockIdx.x * blockDim.x + threadIdx.x;
    if (i >= NNZ) return;
    int v, h;
    if (g_flag[0]) {
        const long long* e = (const long long*)ei_raw;
        v = (int)e[i];
        h = (int)e[NNZ + i];
    } else {
        const int* e = (const int*)ei_raw;
        v = e[i];
        h = e[NNZ + i];
    }
    g_vi[i] = v;
    g_hi[i] = h;
    atomicAdd(&g_cnt_v[v], 1);
    atomicAdd(&g_cnt_e[h], 1);
}

__global__ void k_invdeg() {
    int i = blockIdx.x * blockDim.x + threadIdx.x;
    if (i < N_NODES)  g_inv_v[i] = 1.0f / (float)max(g_cnt_v[i], 1);
    if (i < N_HEDGES) g_inv_e[i] = 1.0f / (float)max(g_cnt_e[i], 1);
}

// ---------------- fp32 tiled GEMM: C[M,N] = A[M,K] * B[K,N] ----------------
// BM=BN=64, BK=16, 256 threads, 4x4 per thread.
__global__ void k_gemm(const float* __restrict__ A, const float* __restrict__ B,
                       float* __restrict__ C, int M, int K, int N) {
    __shared__ float As[16][64];   // As[k][m]
    __shared__ float Bs[16][64];   // Bs[k][n]
    const int t  = threadIdx.x;
    const int tx = t & 15;
    const int ty = t >> 4;

    const int aRow  = t >> 2;          // 0..63
    const int aCol4 = (t & 3) * 4;     // 0,4,8,12
    const int bRow  = t >> 4;          // 0..15
    const int bCol4 = (t & 15) * 4;    // 0..60

    const int gARow = blockIdx.y * 64 + aRow;
    const float* Aptr = A + (size_t)gARow * K + aCol4;
    const float* Bptr = B + (size_t)bRow * N + blockIdx.x * 64 + bCol4;

    float acc[4][4] = {};

    for (int k0 = 0; k0 < K; k0 += 16) {
        float4 av = (gARow < M) ? *(const float4*)(Aptr + k0)
                                : make_float4(0.f, 0.f, 0.f, 0.f);
        float4 bv = *(const float4*)(Bptr + (size_t)k0 * N);
        As[aCol4 + 0][aRow] = av.x;
        As[aCol4 + 1][aRow] = av.y;
        As[aCol4 + 2][aRow] = av.z;
        As[aCol4 + 3][aRow] = av.w;
        *(float4*)&Bs[bRow][bCol4] = bv;
        __syncthreads();

        #pragma unroll
        for (int kk = 0; kk < 16; kk++) {
            float4 a = *(const float4*)&As[kk][ty * 4];
            float4 b = *(const float4*)&Bs[kk][tx * 4];
            float ar[4] = {a.x, a.y, a.z, a.w};
            float br[4] = {b.x, b.y, b.z, b.w};
            #pragma unroll
            for (int i = 0; i < 4; i++)
                #pragma unroll
                for (int j = 0; j < 4; j++)
                    acc[i][j] += ar[i] * br[j];
        }
        __syncthreads();
    }

    const int cRow0 = blockIdx.y * 64 + ty * 4;
    const int cCol  = blockIdx.x * 64 + tx * 4;
    #pragma unroll
    for (int i = 0; i < 4; i++) {
        int r = cRow0 + i;
        if (r < M)
            *(float4*)&C[(size_t)r * N + cCol] =
                make_float4(acc[i][0], acc[i][1], acc[i][2], acc[i][3]);
    }
}

// ---------------- scatter-add (vectorized atomics) ----------------
// dst[drows[n]] += src[srows[n]] * (scale ? scale[srows[n]] : 1)
__global__ void k_scatter(const float* __restrict__ src,
                          const int* __restrict__ srows,
                          const int* __restrict__ drows,
                          float* __restrict__ dst,
                          const float* __restrict__ scale,
                          int c4shift, int total) {
    int idx = blockIdx.x * blockDim.x + threadIdx.x;
    if (idx >= total) return;
    int n = idx >> c4shift;
    int g = idx & ((1 << c4shift) - 1);
    int s = srows[n];
    int d = drows[n];
    float4 v = *(const float4*)(src + (((size_t)s << c4shift) + g) * 4);
    if (scale) {
        float sc = scale[s];
        v.x *= sc; v.y *= sc; v.z *= sc; v.w *= sc;
    }
    float* dp = dst + (((size_t)d << c4shift) + g) * 4;
    asm volatile("red.global.add.v4.f32 [%0], {%1,%2,%3,%4};"
                 :: "l"(dp), "f"(v.x), "f"(v.y), "f"(v.z), "f"(v.w)
                 : "memory");
}

// ---------------- epilogue: out = xv*inv_v[row] + bias[col]; optional ELU ----
__global__ void k_epilogue(const float* __restrict__ xv,
                           const float* __restrict__ inv_v,
                           const float* __restrict__ bias,
                           float* __restrict__ out,
                           int c4shift, int total4, int do_elu) {
    int idx = blockIdx.x * blockDim.x + threadIdx.x;
    if (idx >= total4) return;
    int r = idx >> c4shift;
    int g = idx & ((1 << c4shift) - 1);
    float s = inv_v[r];
    float4 v = *(const float4*)(xv + (size_t)idx * 4);
    float4 b = *(const float4*)(bias + g * 4);
    v.x = v.x * s + b.x;
    v.y = v.y * s + b.y;
    v.z = v.z * s + b.z;
    v.w = v.w * s + b.w;
    if (do_elu) {
        v.x = v.x > 0.f ? v.x : expm1f(v.x);
        v.y = v.y > 0.f ? v.y : expm1f(v.y);
        v.z = v.z > 0.f ? v.z : expm1f(v.z);
        v.w = v.w > 0.f ? v.w : expm1f(v.w);
    }
    ((float4*)out)[idx] = v;
}

// ---------------- host driver ----------------
static inline int cdiv(int a, int b) { return (a + b - 1) / b; }

extern "C" void kernel_launch(void* const* d_in, const int* in_sizes, int n_in,
                              void* d_out, int out_size) {
    const float* x  = (const float*)d_in[0];
    const void*  ei = d_in[1];
    // d_in[2] = edge_weight (all ones; unused by the reference math)
    const float* W1 = (const float*)d_in[3];
    const float* b1 = (const float*)d_in[4];
    const float* W2 = (const float*)d_in[5];
    const float* b2 = (const float*)d_in[6];
    const float* W3 = (const float*)d_in[7];
    const float* b3 = (const float*)d_in[8];

    float *A, *B, *C, *inv_v, *inv_e;
    int *cnt_v, *cnt_e, *vi, *hi;
    cudaGetSymbolAddress((void**)&A, g_bufA);
    cudaGetSymbolAddress((void**)&B, g_bufB);
    cudaGetSymbolAddress((void**)&C, g_bufC);
    cudaGetSymbolAddress((void**)&inv_v, g_inv_v);
    cudaGetSymbolAddress((void**)&inv_e, g_inv_e);
    cudaGetSymbolAddress((void**)&cnt_v, g_cnt_v);
    cudaGetSymbolAddress((void**)&cnt_e, g_cnt_e);
    cudaGetSymbolAddress((void**)&vi, g_vi);
    cudaGetSymbolAddress((void**)&hi, g_hi);

    const int TB = 256;

    // ---- prep: degrees + index conversion ----
    k_zero<<<cdiv(N_NODES / 4, TB), TB>>>((float4*)cnt_v, N_NODES / 4);
    k_zero<<<cdiv(N_HEDGES / 4, TB), TB>>>((float4*)cnt_e, N_HEDGES / 4);
    k_detect<<<1, 32>>>((const int*)ei);
    k_convert<<<cdiv(NNZ, TB), TB>>>(ei);
    k_invdeg<<<cdiv(N_NODES, TB), TB>>>();

    // One layer: gemm -> zero xe -> scatter v->e -> zero xv -> scatter e->v (×1/deg_e)
    //            -> epilogue (×1/deg_v + bias, optional ELU)
    auto layer = [&](const float* hin, const float* W, const float* bias,
                     float* msg, float* xe, float* xv, float* hout,
                     int Cin, int Cout, int elu) {
        dim3 gg(Cout / 64, cdiv(N_NODES, 64));
        k_gemm<<<gg, TB>>>(hin, W, msg, N_NODES, Cin, Cout);
        int shift = (Cout == 256) ? 6 : 5;       // log2(Cout/4)
        int n4e = N_HEDGES * Cout / 4;
        int n4v = N_NODES * Cout / 4;
        int total = NNZ << shift;
        k_zero<<<cdiv(n4e, TB), TB>>>((float4*)xe, n4e);
        k_scatter<<<cdiv(total, TB), TB>>>(msg, vi, hi, xe, nullptr, shift, total);
        k_zero<<<cdiv(n4v, TB), TB>>>((float4*)xv, n4v);
        k_scatter<<<cdiv(total, TB), TB>>>(xe, hi, vi, xv, inv_e, shift, total);
        k_epilogue<<<cdiv(n4v, TB), TB>>>(xv, inv_v, bias, hout, shift, n4v, elu);
    };

    float* out = (float*)d_out;

    // L1: x -> A(msg) -> B(xe) -> C(xv) -> A(h1)
    layer(x, W1, b1, /*msg*/A, /*xe*/B, /*xv*/C, /*hout*/A, F_IN, HID, 1);
    // L2: A -> B(msg) -> C(xe) -> B(xv) -> C(h2)
    layer(A, W2, b2, /*msg*/B, /*xe*/C, /*xv*/B, /*hout*/C, HID, HID, 1);
    // L3: C -> A(msg) -> B(xe) -> d_out(xv) -> d_out (no ELU)
    layer(C, W3, b3, /*msg*/A, /*xe*/B, /*xv*/out, /*hout*/out, HID, F_OUT, 0);
}

// round 2
// speedup vs baseline: 2.0426x; 2.0426x over previous
#include <cuda_runtime.h>
#include <cstdint>
#include <math.h>

#define N_NODES  50000
#define N_HEDGES 50000
#define NNZ      800000
#define F_IN     256
#define HID      256
#define F_OUT    128

// ---------------- scratch (device globals; no allocs allowed) ----------------
__device__ __align__(128) float g_bufA[N_NODES * HID];
__device__ __align__(128) float g_bufB[N_NODES * HID];
__device__ __align__(128) float g_bufC[N_NODES * HID];
__device__ __align__(128) float g_inv_v[N_NODES];
__device__ __align__(128) float g_inv_e[N_HEDGES];
__device__ __align__(128) int   g_cnt_v[N_NODES];
__device__ __align__(128) int   g_cnt_e[N_HEDGES];
__device__ __align__(128) int   g_cur_v[N_NODES];
__device__ __align__(128) int   g_cur_e[N_HEDGES];
__device__ __align__(128) int   g_off_v[N_NODES + 1];
__device__ __align__(128) int   g_off_e[N_HEDGES + 1];
__device__ __align__(128) int   g_vi[NNZ];
__device__ __align__(128) int   g_hi[NNZ];
__device__ __align__(128) int   g_nbr_e[NNZ];  // per hyperedge: member node ids
__device__ __align__(128) int   g_nbr_v[NNZ];  // per node: incident hyperedge ids
__device__ int g_flag[1];

// ---------------- small utility kernels ----------------
__global__ void k_zero_i(int* p, int n) {
    int i = blockIdx.x * blockDim.x + threadIdx.x;
    if (i < n) p[i] = 0;
}

// Detect whether edge_index is int64 (odd 32-bit words of small nonneg values are 0)
__global__ void k_detect(const int* __restrict__ ei) {
    if (blockIdx.x == 0 && threadIdx.x == 0) {
        int z = 0;
        #pragma unroll
        for (int i = 1; i < 64; i += 2) z |= ei[i];
        g_flag[0] = (z == 0) ? 1 : 0;
    }
}

// Convert edge_index to int32 vi/hi and count degrees
__global__ void k_convert(const void* __restrict__ ei_raw) {
    int i = blockIdx.x * blockDim.x + threadIdx.x;
    if (i >= NNZ) return;
    int v, h;
    if (g_flag[0]) {
        const long long* e = (const long long*)ei_raw;
        v = (int)e[i];
        h = (int)e[NNZ + i];
    } else {
        const int* e = (const int*)ei_raw;
        v = e[i];
        h = e[NNZ + i];
    }
    g_vi[i] = v;
    g_hi[i] = h;
    atomicAdd(&g_cnt_v[v], 1);
    atomicAdd(&g_cnt_e[h], 1);
}

__global__ void k_invdeg() {
    int i = blockIdx.x * blockDim.x + threadIdx.x;
    if (i < N_NODES)  g_inv_v[i] = 1.0f / (float)max(g_cnt_v[i], 1);
    if (i < N_HEDGES) g_inv_e[i] = 1.0f / (float)max(g_cnt_e[i], 1);
}

// Exclusive scan of 50000 counts -> offsets. One block per array (0: e, 1: v).
__global__ void k_scan() {
    const int n = 50000;
    const int* cnt = blockIdx.x ? g_cnt_v : g_cnt_e;
    int* off       = blockIdx.x ? g_off_v : g_off_e;
    __shared__ int partial[1024];
    int t = threadIdx.x;
    const int PER = (n + 1023) / 1024;  // 49
    int base = t * PER;
    int s = 0;
    for (int i = 0; i < PER; i++) {
        int idx = base + i;
        if (idx < n) s += cnt[idx];
    }
    partial[t] = s;
    __syncthreads();
    // Hillis-Steele inclusive scan
    for (int d = 1; d < 1024; d <<= 1) {
        int v = (t >= d) ? partial[t - d] : 0;
        __syncthreads();
        partial[t] += v;
        __syncthreads();
    }
    int run = (t == 0) ? 0 : partial[t - 1];
    for (int i = 0; i < PER; i++) {
        int idx = base + i;
        if (idx < n) { off[idx] = run; run += cnt[idx]; }
    }
    if (t == 1023) off[n] = run;
}

// Fill CSR neighbor lists
__global__ void k_fill() {
    int i = blockIdx.x * blockDim.x + threadIdx.x;
    if (i >= NNZ) return;
    int v = g_vi[i], h = g_hi[i];
    int pe = g_off_e[h] + atomicAdd(&g_cur_e[h], 1);
    g_nbr_e[pe] = v;
    int pv = g_off_v[v] + atomicAdd(&g_cur_v[v], 1);
    g_nbr_v[pv] = h;
}

// ---------------- fp32 SGEMM: C[M,N] = A[M,K]*B[K,N], 128x128x8, 8x8/thread ----
__global__ __launch_bounds__(256, 2)
void k_sgemm(const float* __restrict__ A, const float* __restrict__ B,
             float* __restrict__ C, int M, int K, int N) {
    __shared__ float As[2][8][128];
    __shared__ float Bs[2][8][128];
    const int t = threadIdx.x;
    const int arow = t >> 1, acol = (t & 1) * 4;     // A tile: 128 rows x 8 cols
    const int brow = t >> 5, bcol = (t & 31) * 4;    // B tile: 8 rows x 128 cols
    const int bm = blockIdx.y * 128, bn = blockIdx.x * 128;
    const bool arow_ok = (bm + arow) < M;
    const float* Ap = A + (size_t)(bm + arow) * K + acol;
    const float* Bp = B + (size_t)brow * N + bn + bcol;

    const int tx = t & 15, ty = t >> 4;

    float acc[8][8] = {};
    float4 aReg, bReg;

    aReg = arow_ok ? *(const float4*)Ap : make_float4(0.f, 0.f, 0.f, 0.f);
    bReg = *(const float4*)Bp;
    As[0][acol + 0][arow] = aReg.x;
    As[0][acol + 1][arow] = aReg.y;
    As[0][acol + 2][arow] = aReg.z;
    As[0][acol + 3][arow] = aReg.w;
    *(float4*)&Bs[0][brow][bcol] = bReg;
    __syncthreads();

    const int nk = K >> 3;
    for (int kt = 0; kt < nk; kt++) {
        const int cur = kt & 1, nxt = cur ^ 1;
        if (kt + 1 < nk) {
            aReg = arow_ok ? *(const float4*)(Ap + (kt + 1) * 8)
                           : make_float4(0.f, 0.f, 0.f, 0.f);
            bReg = *(const float4*)(Bp + (size_t)(kt + 1) * 8 * N);
        }
        #pragma unroll
        for (int kk = 0; kk < 8; kk++) {
            float a[8], b[8];
            *(float4*)&a[0] = *(const float4*)&As[cur][kk][ty * 4];
            *(float4*)&a[4] = *(const float4*)&As[cur][kk][64 + ty * 4];
            *(float4*)&b[0] = *(const float4*)&Bs[cur][kk][tx * 4];
            *(float4*)&b[4] = *(const float4*)&Bs[cur][kk][64 + tx * 4];
            #pragma unroll
            for (int i = 0; i < 8; i++)
                #pragma unroll
                for (int j = 0; j < 8; j++)
                    acc[i][j] += a[i] * b[j];
        }
        if (kt + 1 < nk) {
            As[nxt][acol + 0][arow] = aReg.x;
            As[nxt][acol + 1][arow] = aReg.y;
            As[nxt][acol + 2][arow] = aReg.z;
            As[nxt][acol + 3][arow] = aReg.w;
            *(float4*)&Bs[nxt][brow][bcol] = bReg;
        }
        __syncthreads();
    }

    #pragma unroll
    for (int i = 0; i < 8; i++) {
        int r = bm + ((i < 4) ? (ty * 4 + i) : (64 + ty * 4 + i - 4));
        if (r < M) {
            float* Cp = C + (size_t)r * N + bn;
            *(float4*)(Cp + tx * 4) =
                make_float4(acc[i][0], acc[i][1], acc[i][2], acc[i][3]);
            *(float4*)(Cp + 64 + tx * 4) =
                make_float4(acc[i][4], acc[i][5], acc[i][6], acc[i][7]);
        }
    }
}

// ---------------- CSR gather: dst[r] = (sum_{n in nbr[r]} src[n]) * dscale[r] (+bias, ELU) ----
template<int C4, int RPB>
__global__ __launch_bounds__(C4 * RPB)
void k_gather(const float4* __restrict__ src,
              const int* __restrict__ off,
              const int* __restrict__ nbr,
              const float* __restrict__ dscale,
              const float* __restrict__ bias,
              float4* __restrict__ dst,
              int nrows, int do_elu) {
    const int group = threadIdx.x / C4;
    const int lane  = threadIdx.x % C4;
    const int row = blockIdx.x * RPB + group;
    if (row >= nrows) return;
    const int s0 = off[row], s1 = off[row + 1];
    float4 acc = make_float4(0.f, 0.f, 0.f, 0.f);
    int j = s0;
    for (; j + 1 < s1; j += 2) {
        int n0 = __ldg(&nbr[j]);
        int n1 = __ldg(&nbr[j + 1]);
        float4 a = src[(size_t)n0 * C4 + lane];
        float4 b = src[(size_t)n1 * C4 + lane];
        acc.x += a.x + b.x;
        acc.y += a.y + b.y;
        acc.z += a.z + b.z;
        acc.w += a.w + b.w;
    }
    if (j < s1) {
        int n0 = __ldg(&nbr[j]);
        float4 a = src[(size_t)n0 * C4 + lane];
        acc.x += a.x; acc.y += a.y; acc.z += a.z; acc.w += a.w;
    }
    float s = dscale[row];
    acc.x *= s; acc.y *= s; acc.z *= s; acc.w *= s;
    if (bias) {
        float4 b = ((const float4*)bias)[lane];
        acc.x += b.x; acc.y += b.y; acc.z += b.z; acc.w += b.w;
        if (do_elu) {
            acc.x = acc.x > 0.f ? acc.x : expm1f(acc.x);
            acc.y = acc.y > 0.f ? acc.y : expm1f(acc.y);
            acc.z = acc.z > 0.f ? acc.z : expm1f(acc.z);
            acc.w = acc.w > 0.f ? acc.w : expm1f(acc.w);
        }
    }
    dst[(size_t)row * C4 + lane] = acc;
}

// ---------------- host driver ----------------
static inline int cdiv(int a, int b) { return (a + b - 1) / b; }

extern "C" void kernel_launch(void* const* d_in, const int* in_sizes, int n_in,
                              void* d_out, int out_size) {
    const float* x  = (const float*)d_in[0];
    const void*  ei = d_in[1];
    // d_in[2] = edge_weight (all ones; unused by reference math)
    const float* W1 = (const float*)d_in[3];
    const float* b1 = (const float*)d_in[4];
    const float* W2 = (const float*)d_in[5];
    const float* b2 = (const float*)d_in[6];
    const float* W3 = (const float*)d_in[7];
    const float* b3 = (const float*)d_in[8];

    float *A, *B, *C, *inv_v, *inv_e;
    int *cnt_v, *cnt_e, *cur_v, *cur_e, *off_v, *off_e, *nbr_v, *nbr_e;
    cudaGetSymbolAddress((void**)&A, g_bufA);
    cudaGetSymbolAddress((void**)&B, g_bufB);
    cudaGetSymbolAddress((void**)&C, g_bufC);
    cudaGetSymbolAddress((void**)&inv_v, g_inv_v);
    cudaGetSymbolAddress((void**)&inv_e, g_inv_e);
    cudaGetSymbolAddress((void**)&cnt_v, g_cnt_v);
    cudaGetSymbolAddress((void**)&cnt_e, g_cnt_e);
    cudaGetSymbolAddress((void**)&cur_v, g_cur_v);
    cudaGetSymbolAddress((void**)&cur_e, g_cur_e);
    cudaGetSymbolAddress((void**)&off_v, g_off_v);
    cudaGetSymbolAddress((void**)&off_e, g_off_e);
    cudaGetSymbolAddress((void**)&nbr_v, g_nbr_v);
    cudaGetSymbolAddress((void**)&nbr_e, g_nbr_e);

    const int TB = 256;

    // ---- prep: degrees, CSR build ----
    k_zero_i<<<cdiv(N_NODES, TB), TB>>>(cnt_v, N_NODES);
    k_zero_i<<<cdiv(N_HEDGES, TB), TB>>>(cnt_e, N_HEDGES);
    k_zero_i<<<cdiv(N_NODES, TB), TB>>>(cur_v, N_NODES);
    k_zero_i<<<cdiv(N_HEDGES, TB), TB>>>(cur_e, N_HEDGES);
    k_detect<<<1, 32>>>((const int*)ei);
    k_convert<<<cdiv(NNZ, TB), TB>>>(ei);
    k_scan<<<2, 1024>>>();
    k_fill<<<cdiv(NNZ, TB), TB>>>();
    k_invdeg<<<cdiv(N_NODES, TB), TB>>>();

    // One layer: gemm -> gather v->e (x inv_e at write) -> gather e->v (x inv_v + bias + ELU)
    auto layer = [&](const float* hin, const float* W, const float* bias,
                     float* msg, float* xe, float* hout,
                     int Cin, int Cout, int elu) {
        dim3 gg(Cout / 128, cdiv(N_NODES, 128));
        k_sgemm<<<gg, 256>>>(hin, W, msg, N_NODES, Cin, Cout);
        if (Cout == 256) {
            k_gather<64, 4><<<cdiv(N_HEDGES, 4), 256>>>(
                (const float4*)msg, off_e, nbr_e, inv_e, nullptr,
                (float4*)xe, N_HEDGES, 0);
            k_gather<64, 4><<<cdiv(N_NODES, 4), 256>>>(
                (const float4*)xe, off_v, nbr_v, inv_v, bias,
                (float4*)hout, N_NODES, elu);
        } else {
            k_gather<32, 8><<<cdiv(N_HEDGES, 8), 256>>>(
                (const float4*)msg, off_e, nbr_e, inv_e, nullptr,
                (float4*)xe, N_HEDGES, 0);
            k_gather<32, 8><<<cdiv(N_NODES, 8), 256>>>(
                (const float4*)xe, off_v, nbr_v, inv_v, bias,
                (float4*)hout, N_NODES, elu);
        }
    };

    float* out = (float*)d_out;

    // L1: x -> A(msg) -> B(xe) -> C(h1)
    layer(x, W1, b1, A, B, C, F_IN, HID, 1);
    // L2: C -> A(msg) -> B(xe) -> C(h2)   (A,B reusable; hout C overwrites input after reads done? no:
    //     gather e->v reads xe=B and writes C; input C already consumed by gemm into A. safe.)
    layer(C, W2, b2, A, B, C, HID, HID, 1);
    // L3: C -> A(msg) -> B(xe) -> d_out  (no ELU)
    layer(C, W3, b3, A, B, out, HID, F_OUT, 0);
}

// round 3
// speedup vs baseline: 2.7462x; 1.3444x over previous
#include <cuda_runtime.h>
#include <cstdint>
#include <math.h>

#define N_NODES  50000
#define N_HEDGES 50000
#define NNZ      800000
#define F_IN     256
#define HID      256
#define F_OUT    128

// ---------------- scratch (device globals; no allocs allowed) ----------------
__device__ __align__(128) float g_bufA[N_NODES * HID];
__device__ __align__(128) float g_bufB[N_NODES * HID];
__device__ __align__(128) float g_bufC[N_NODES * HID];
__device__ __align__(128) float g_inv_v[N_NODES];
__device__ __align__(128) float g_inv_e[N_HEDGES];
__device__ __align__(128) int   g_cnt_v[N_NODES];
__device__ __align__(128) int   g_cnt_e[N_HEDGES];
__device__ __align__(128) int   g_cur_v[N_NODES];
__device__ __align__(128) int   g_cur_e[N_HEDGES];
__device__ __align__(128) int   g_off_v[N_NODES + 1];
__device__ __align__(128) int   g_off_e[N_HEDGES + 1];
__device__ __align__(128) int   g_vi[NNZ];
__device__ __align__(128) int   g_hi[NNZ];
__device__ __align__(128) int   g_nbr_e[NNZ];
__device__ __align__(128) int   g_nbr_v[NNZ];
__device__ int g_flag[1];

// ---------------- small utility kernels ----------------
__global__ void k_zero_i(int* p, int n) {
    int i = blockIdx.x * blockDim.x + threadIdx.x;
    if (i < n) p[i] = 0;
}

__global__ void k_detect(const int* __restrict__ ei) {
    if (blockIdx.x == 0 && threadIdx.x == 0) {
        int z = 0;
        #pragma unroll
        for (int i = 1; i < 64; i += 2) z |= ei[i];
        g_flag[0] = (z == 0) ? 1 : 0;
    }
}

__global__ void k_convert(const void* __restrict__ ei_raw) {
    int i = blockIdx.x * blockDim.x + threadIdx.x;
    if (i >= NNZ) return;
    int v, h;
    if (g_flag[0]) {
        const long long* e = (const long long*)ei_raw;
        v = (int)e[i];
        h = (int)e[NNZ + i];
    } else {
        const int* e = (const int*)ei_raw;
        v = e[i];
        h = e[NNZ + i];
    }
    g_vi[i] = v;
    g_hi[i] = h;
    atomicAdd(&g_cnt_v[v], 1);
    atomicAdd(&g_cnt_e[h], 1);
}

__global__ void k_invdeg() {
    int i = blockIdx.x * blockDim.x + threadIdx.x;
    if (i < N_NODES)  g_inv_v[i] = 1.0f / (float)max(g_cnt_v[i], 1);
    if (i < N_HEDGES) g_inv_e[i] = 1.0f / (float)max(g_cnt_e[i], 1);
}

__global__ void k_scan() {
    const int n = 50000;
    const int* cnt = blockIdx.x ? g_cnt_v : g_cnt_e;
    int* off       = blockIdx.x ? g_off_v : g_off_e;
    __shared__ int partial[1024];
    int t = threadIdx.x;
    const int PER = (n + 1023) / 1024;
    int base = t * PER;
    int s = 0;
    for (int i = 0; i < PER; i++) {
        int idx = base + i;
        if (idx < n) s += cnt[idx];
    }
    partial[t] = s;
    __syncthreads();
    for (int d = 1; d < 1024; d <<= 1) {
        int v = (t >= d) ? partial[t - d] : 0;
        __syncthreads();
        partial[t] += v;
        __syncthreads();
    }
    int run = (t == 0) ? 0 : partial[t - 1];
    for (int i = 0; i < PER; i++) {
        int idx = base + i;
        if (idx < n) { off[idx] = run; run += cnt[idx]; }
    }
    if (t == 1023) off[n] = run;
}

__global__ void k_fill() {
    int i = blockIdx.x * blockDim.x + threadIdx.x;
    if (i >= NNZ) return;
    int v = g_vi[i], h = g_hi[i];
    int pe = g_off_e[h] + atomicAdd(&g_cur_e[h], 1);
    g_nbr_e[pe] = v;
    int pv = g_off_v[v] + atomicAdd(&g_cur_v[v], 1);
    g_nbr_v[pv] = h;
}

// ---------------- TF32 tensor-core GEMM: C[M,N] = A[M,K]*B[K,N] ----------------
// Block 128x128, k-chunk 8, 8 warps (2x4), warp tile 64x32, mma.m16n8k8.tf32.
__device__ __forceinline__ uint32_t f2tf32(float x) {
    uint32_t r;
    asm("cvt.rna.tf32.f32 %0, %1;" : "=r"(r) : "f"(x));
    return r;
}

__global__ __launch_bounds__(256, 2)
void k_tgemm(const float* __restrict__ A, const float* __restrict__ B,
             float* __restrict__ C, int M, int K, int N) {
    __shared__ uint32_t As[2][8][132];   // [k][m], pad 4
    __shared__ uint32_t Bs[2][8][132];   // [k][n], pad 4
    const int t = threadIdx.x;
    const int lane = t & 31;
    const int warp = t >> 5;
    const int warp_m = (warp & 1) * 64;   // 2 warps along M
    const int warp_n = (warp >> 1) * 32;  // 4 warps along N
    const int gid = lane >> 2;            // groupID 0..7
    const int tg  = lane & 3;             // tid-in-group 0..3

    const int arow = t >> 1, acol = (t & 1) * 4;
    const int brow = t >> 5, bcol = (t & 31) * 4;
    const int bm = blockIdx.y * 128, bn = blockIdx.x * 128;
    const bool arow_ok = (bm + arow) < M;
    const float* Ap = A + (size_t)(bm + arow) * K + acol;
    const float* Bp = B + (size_t)brow * N + bn + bcol;

    float acc[4][4][4] = {};  // [mt][nt][reg]
    float4 aReg, bReg;

    aReg = arow_ok ? *(const float4*)Ap : make_float4(0.f, 0.f, 0.f, 0.f);
    bReg = *(const float4*)Bp;
    As[0][acol + 0][arow] = f2tf32(aReg.x);
    As[0][acol + 1][arow] = f2tf32(aReg.y);
    As[0][acol + 2][arow] = f2tf32(aReg.z);
    As[0][acol + 3][arow] = f2tf32(aReg.w);
    Bs[0][brow][bcol + 0] = f2tf32(bReg.x);
    Bs[0][brow][bcol + 1] = f2tf32(bReg.y);
    Bs[0][brow][bcol + 2] = f2tf32(bReg.z);
    Bs[0][brow][bcol + 3] = f2tf32(bReg.w);
    __syncthreads();

    const int nk = K >> 3;
    for (int kt = 0; kt < nk; kt++) {
        const int cur = kt & 1, nxt = cur ^ 1;
        if (kt + 1 < nk) {
            aReg = arow_ok ? *(const float4*)(Ap + (kt + 1) * 8)
                           : make_float4(0.f, 0.f, 0.f, 0.f);
            bReg = *(const float4*)(Bp + (size_t)(kt + 1) * 8 * N);
        }

        uint32_t af[4][4], bf[4][2];
        #pragma unroll
        for (int mt = 0; mt < 4; mt++) {
            int r = warp_m + mt * 16 + gid;
            af[mt][0] = As[cur][tg][r];
            af[mt][1] = As[cur][tg][r + 8];
            af[mt][2] = As[cur][tg + 4][r];
            af[mt][3] = As[cur][tg + 4][r + 8];
        }
        #pragma unroll
        for (int nt = 0; nt < 4; nt++) {
            int c = warp_n + nt * 8 + gid;
            bf[nt][0] = Bs[cur][tg][c];
            bf[nt][1] = Bs[cur][tg + 4][c];
        }
        #pragma unroll
        for (int mt = 0; mt < 4; mt++)
            #pragma unroll
            for (int nt = 0; nt < 4; nt++) {
                asm volatile(
                    "mma.sync.aligned.m16n8k8.row.col.f32.tf32.tf32.f32 "
                    "{%0,%1,%2,%3}, {%4,%5,%6,%7}, {%8,%9}, {%0,%1,%2,%3};"
                    : "+f"(acc[mt][nt][0]), "+f"(acc[mt][nt][1]),
                      "+f"(acc[mt][nt][2]), "+f"(acc[mt][nt][3])
                    : "r"(af[mt][0]), "r"(af[mt][1]), "r"(af[mt][2]), "r"(af[mt][3]),
                      "r"(bf[nt][0]), "r"(bf[nt][1]));
            }

        if (kt + 1 < nk) {
            As[nxt][acol + 0][arow] = f2tf32(aReg.x);
            As[nxt][acol + 1][arow] = f2tf32(aReg.y);
            As[nxt][acol + 2][arow] = f2tf32(aReg.z);
            As[nxt][acol + 3][arow] = f2tf32(aReg.w);
            Bs[nxt][brow][bcol + 0] = f2tf32(bReg.x);
            Bs[nxt][brow][bcol + 1] = f2tf32(bReg.y);
            Bs[nxt][brow][bcol + 2] = f2tf32(bReg.z);
            Bs[nxt][brow][bcol + 3] = f2tf32(bReg.w);
        }
        __syncthreads();
    }

    // epilogue: d0,d1 -> (row, col*2 .. +1); d2,d3 -> (row+8, ...)
    #pragma unroll
    for (int mt = 0; mt < 4; mt++) {
        int r0 = bm + warp_m + mt * 16 + gid;
        #pragma unroll
        for (int nt = 0; nt < 4; nt++) {
            int c0 = bn + warp_n + nt * 8 + tg * 2;
            if (r0 < M)
                *(float2*)&C[(size_t)r0 * N + c0] =
                    make_float2(acc[mt][nt][0], acc[mt][nt][1]);
            if (r0 + 8 < M)
                *(float2*)&C[(size_t)(r0 + 8) * N + c0] =
                    make_float2(acc[mt][nt][2], acc[mt][nt][3]);
        }
    }
}

// ---------------- CSR gather ----------------
template<int C4, int RPB>
__global__ __launch_bounds__(C4 * RPB)
void k_gather(const float4* __restrict__ src,
              const int* __restrict__ off,
              const int* __restrict__ nbr,
              const float* __restrict__ dscale,
              const float* __restrict__ bias,
              float4* __restrict__ dst,
              int nrows, int do_elu) {
    const int group = threadIdx.x / C4;
    const int lane  = threadIdx.x % C4;
    const int row = blockIdx.x * RPB + group;
    if (row >= nrows) return;
    const int s0 = off[row], s1 = off[row + 1];
    float4 acc = make_float4(0.f, 0.f, 0.f, 0.f);
    int j = s0;
    for (; j + 1 < s1; j += 2) {
        int n0 = __ldg(&nbr[j]);
        int n1 = __ldg(&nbr[j + 1]);
        float4 a = src[(size_t)n0 * C4 + lane];
        float4 b = src[(size_t)n1 * C4 + lane];
        acc.x += a.x + b.x;
        acc.y += a.y + b.y;
        acc.z += a.z + b.z;
        acc.w += a.w + b.w;
    }
    if (j < s1) {
        int n0 = __ldg(&nbr[j]);
        float4 a = src[(size_t)n0 * C4 + lane];
        acc.x += a.x; acc.y += a.y; acc.z += a.z; acc.w += a.w;
    }
    float s = dscale[row];
    acc.x *= s; acc.y *= s; acc.z *= s; acc.w *= s;
    if (bias) {
        float4 b = ((const float4*)bias)[lane];
        acc.x += b.x; acc.y += b.y; acc.z += b.z; acc.w += b.w;
        if (do_elu) {
            acc.x = acc.x > 0.f ? acc.x : expm1f(acc.x);
            acc.y = acc.y > 0.f ? acc.y : expm1f(acc.y);
            acc.z = acc.z > 0.f ? acc.z : expm1f(acc.z);
            acc.w = acc.w > 0.f ? acc.w : expm1f(acc.w);
        }
    }
    dst[(size_t)row * C4 + lane] = acc;
}

// ---------------- host driver ----------------
static inline int cdiv(int a, int b) { return (a + b - 1) / b; }

extern "C" void kernel_launch(void* const* d_in, const int* in_sizes, int n_in,
                              void* d_out, int out_size) {
    const float* x  = (const float*)d_in[0];
    const void*  ei = d_in[1];
    const float* W1 = (const float*)d_in[3];
    const float* b1 = (const float*)d_in[4];
    const float* W2 = (const float*)d_in[5];
    const float* b2 = (const float*)d_in[6];
    const float* W3 = (const float*)d_in[7];
    const float* b3 = (const float*)d_in[8];

    float *A, *B, *C, *inv_v, *inv_e;
    int *cnt_v, *cnt_e, *cur_v, *cur_e, *off_v, *off_e, *nbr_v, *nbr_e;
    cudaGetSymbolAddress((void**)&A, g_bufA);
    cudaGetSymbolAddress((void**)&B, g_bufB);
    cudaGetSymbolAddress((void**)&C, g_bufC);
    cudaGetSymbolAddress((void**)&inv_v, g_inv_v);
    cudaGetSymbolAddress((void**)&inv_e, g_inv_e);
    cudaGetSymbolAddress((void**)&cnt_v, g_cnt_v);
    cudaGetSymbolAddress((void**)&cnt_e, g_cnt_e);
    cudaGetSymbolAddress((void**)&cur_v, g_cur_v);
    cudaGetSymbolAddress((void**)&cur_e, g_cur_e);
    cudaGetSymbolAddress((void**)&off_v, g_off_v);
    cudaGetSymbolAddress((void**)&off_e, g_off_e);
    cudaGetSymbolAddress((void**)&nbr_v, g_nbr_v);
    cudaGetSymbolAddress((void**)&nbr_e, g_nbr_e);

    const int TB = 256;

    k_zero_i<<<cdiv(N_NODES, TB), TB>>>(cnt_v, N_NODES);
    k_zero_i<<<cdiv(N_HEDGES, TB), TB>>>(cnt_e, N_HEDGES);
    k_zero_i<<<cdiv(N_NODES, TB), TB>>>(cur_v, N_NODES);
    k_zero_i<<<cdiv(N_HEDGES, TB), TB>>>(cur_e, N_HEDGES);
    k_detect<<<1, 32>>>((const int*)ei);
    k_convert<<<cdiv(NNZ, TB), TB>>>(ei);
    k_scan<<<2, 1024>>>();
    k_fill<<<cdiv(NNZ, TB), TB>>>();
    k_invdeg<<<cdiv(N_NODES, TB), TB>>>();

    auto layer = [&](const float* hin, const float* W, const float* bias,
                     float* msg, float* xe, float* hout,
                     int Cin, int Cout, int elu) {
        dim3 gg(Cout / 128, cdiv(N_NODES, 128));
        k_tgemm<<<gg, 256>>>(hin, W, msg, N_NODES, Cin, Cout);
        if (Cout == 256) {
            k_gather<64, 4><<<cdiv(N_HEDGES, 4), 256>>>(
                (const float4*)msg, off_e, nbr_e, inv_e, nullptr,
                (float4*)xe, N_HEDGES, 0);
            k_gather<64, 4><<<cdiv(N_NODES, 4), 256>>>(
                (const float4*)xe, off_v, nbr_v, inv_v, bias,
                (float4*)hout, N_NODES, elu);
        } else {
            k_gather<32, 8><<<cdiv(N_HEDGES, 8), 256>>>(
                (const float4*)msg, off_e, nbr_e, inv_e, nullptr,
                (float4*)xe, N_HEDGES, 0);
            k_gather<32, 8><<<cdiv(N_NODES, 8), 256>>>(
                (const float4*)xe, off_v, nbr_v, inv_v, bias,
                (float4*)hout, N_NODES, elu);
        }
    };

    float* out = (float*)d_out;

    layer(x, W1, b1, A, B, C, F_IN, HID, 1);
    layer(C, W2, b2, A, B, C, HID, HID, 1);
    layer(C, W3, b3, A, B, out, HID, F_OUT, 0);
}

// round 4
// speedup vs baseline: 3.1851x; 1.1598x over previous
#include <cuda_runtime.h>
#include <cuda_fp16.h>
#include <cstdint>
#include <math.h>

#define N_NODES  50000
#define N_HEDGES 50000
#define NNZ      800000
#define F_IN     256
#define HID      256
#define F_OUT    128

// ---------------- scratch (device globals; no allocs allowed) ----------------
__device__ __align__(128) float g_bufA[N_NODES * HID];  // msg (fp16, reinterpreted)
__device__ __align__(128) float g_bufB[N_NODES * HID];  // xe  (fp16, reinterpreted)
__device__ __align__(128) float g_bufC[N_NODES * HID];  // h   (fp32)
__device__ __align__(128) float g_inv_v[N_NODES];
__device__ __align__(128) float g_inv_e[N_HEDGES];
__device__ __align__(128) int   g_cnt_v[N_NODES];
__device__ __align__(128) int   g_cnt_e[N_HEDGES];
__device__ __align__(128) int   g_cur_v[N_NODES];
__device__ __align__(128) int   g_cur_e[N_HEDGES];
__device__ __align__(128) int   g_off_v[N_NODES + 1];
__device__ __align__(128) int   g_off_e[N_HEDGES + 1];
__device__ __align__(128) int   g_vi[NNZ];
__device__ __align__(128) int   g_hi[NNZ];
__device__ __align__(128) int   g_nbr_e[NNZ];
__device__ __align__(128) int   g_nbr_v[NNZ];
__device__ int g_flag[1];

// ---------------- small utility kernels ----------------
__global__ void k_zero_i(int* p, int n) {
    int i = blockIdx.x * blockDim.x + threadIdx.x;
    if (i < n) p[i] = 0;
}

__global__ void k_detect(const int* __restrict__ ei) {
    if (blockIdx.x == 0 && threadIdx.x == 0) {
        int z = 0;
        #pragma unroll
        for (int i = 1; i < 64; i += 2) z |= ei[i];
        g_flag[0] = (z == 0) ? 1 : 0;
    }
}

__global__ void k_convert(const void* __restrict__ ei_raw) {
    int i = blockIdx.x * blockDim.x + threadIdx.x;
    if (i >= NNZ) return;
    int v, h;
    if (g_flag[0]) {
        const long long* e = (const long long*)ei_raw;
        v = (int)e[i];
        h = (int)e[NNZ + i];
    } else {
        const int* e = (const int*)ei_raw;
        v = e[i];
        h = e[NNZ + i];
    }
    g_vi[i] = v;
    g_hi[i] = h;
    atomicAdd(&g_cnt_v[v], 1);
    atomicAdd(&g_cnt_e[h], 1);
}

__global__ void k_invdeg() {
    int i = blockIdx.x * blockDim.x + threadIdx.x;
    if (i < N_NODES)  g_inv_v[i] = 1.0f / (float)max(g_cnt_v[i], 1);
    if (i < N_HEDGES) g_inv_e[i] = 1.0f / (float)max(g_cnt_e[i], 1);
}

__global__ void k_scan() {
    const int n = 50000;
    const int* cnt = blockIdx.x ? g_cnt_v : g_cnt_e;
    int* off       = blockIdx.x ? g_off_v : g_off_e;
    __shared__ int partial[1024];
    int t = threadIdx.x;
    const int PER = (n + 1023) / 1024;
    int base = t * PER;
    int s = 0;
    for (int i = 0; i < PER; i++) {
        int idx = base + i;
        if (idx < n) s += cnt[idx];
    }
    partial[t] = s;
    __syncthreads();
    for (int d = 1; d < 1024; d <<= 1) {
        int v = (t >= d) ? partial[t - d] : 0;
        __syncthreads();
        partial[t] += v;
        __syncthreads();
    }
    int run = (t == 0) ? 0 : partial[t - 1];
    for (int i = 0; i < PER; i++) {
        int idx = base + i;
        if (idx < n) { off[idx] = run; run += cnt[idx]; }
    }
    if (t == 1023) off[n] = run;
}

__global__ void k_fill() {
    int i = blockIdx.x * blockDim.x + threadIdx.x;
    if (i >= NNZ) return;
    int v = g_vi[i], h = g_hi[i];
    int pe = g_off_e[h] + atomicAdd(&g_cur_e[h], 1);
    g_nbr_e[pe] = v;
    int pv = g_off_v[v] + atomicAdd(&g_cur_v[v], 1);
    g_nbr_v[pv] = h;
}

// ---------------- TF32 tensor-core GEMM, fp16 output ----------------
__device__ __forceinline__ uint32_t f2tf32(float x) {
    uint32_t r;
    asm("cvt.rna.tf32.f32 %0, %1;" : "=r"(r) : "f"(x));
    return r;
}

__global__ __launch_bounds__(256, 2)
void k_tgemm(const float* __restrict__ A, const float* __restrict__ B,
             __half* __restrict__ C, int M, int K, int N) {
    __shared__ uint32_t As[2][8][132];
    __shared__ uint32_t Bs[2][8][132];
    const int t = threadIdx.x;
    const int lane = t & 31;
    const int warp = t >> 5;
    const int warp_m = (warp & 1) * 64;
    const int warp_n = (warp >> 1) * 32;
    const int gid = lane >> 2;
    const int tg  = lane & 3;

    const int arow = t >> 1, acol = (t & 1) * 4;
    const int brow = t >> 5, bcol = (t & 31) * 4;
    const int bm = blockIdx.y * 128, bn = blockIdx.x * 128;
    const bool arow_ok = (bm + arow) < M;
    const float* Ap = A + (size_t)(bm + arow) * K + acol;
    const float* Bp = B + (size_t)brow * N + bn + bcol;

    float acc[4][4][4] = {};
    float4 aReg, bReg;

    aReg = arow_ok ? *(const float4*)Ap : make_float4(0.f, 0.f, 0.f, 0.f);
    bReg = *(const float4*)Bp;
    As[0][acol + 0][arow] = f2tf32(aReg.x);
    As[0][acol + 1][arow] = f2tf32(aReg.y);
    As[0][acol + 2][arow] = f2tf32(aReg.z);
    As[0][acol + 3][arow] = f2tf32(aReg.w);
    Bs[0][brow][bcol + 0] = f2tf32(bReg.x);
    Bs[0][brow][bcol + 1] = f2tf32(bReg.y);
    Bs[0][brow][bcol + 2] = f2tf32(bReg.z);
    Bs[0][brow][bcol + 3] = f2tf32(bReg.w);
    __syncthreads();

    const int nk = K >> 3;
    for (int kt = 0; kt < nk; kt++) {
        const int cur = kt & 1, nxt = cur ^ 1;
        if (kt + 1 < nk) {
            aReg = arow_ok ? *(const float4*)(Ap + (kt + 1) * 8)
                           : make_float4(0.f, 0.f, 0.f, 0.f);
            bReg = *(const float4*)(Bp + (size_t)(kt + 1) * 8 * N);
        }

        uint32_t af[4][4], bf[4][2];
        #pragma unroll
        for (int mt = 0; mt < 4; mt++) {
            int r = warp_m + mt * 16 + gid;
            af[mt][0] = As[cur][tg][r];
            af[mt][1] = As[cur][tg][r + 8];
            af[mt][2] = As[cur][tg + 4][r];
            af[mt][3] = As[cur][tg + 4][r + 8];
        }
        #pragma unroll
        for (int nt = 0; nt < 4; nt++) {
            int c = warp_n + nt * 8 + gid;
            bf[nt][0] = Bs[cur][tg][c];
            bf[nt][1] = Bs[cur][tg + 4][c];
        }
        #pragma unroll
        for (int mt = 0; mt < 4; mt++)
            #pragma unroll
            for (int nt = 0; nt < 4; nt++) {
                asm volatile(
                    "mma.sync.aligned.m16n8k8.row.col.f32.tf32.tf32.f32 "
                    "{%0,%1,%2,%3}, {%4,%5,%6,%7}, {%8,%9}, {%0,%1,%2,%3};"
                    : "+f"(acc[mt][nt][0]), "+f"(acc[mt][nt][1]),
                      "+f"(acc[mt][nt][2]), "+f"(acc[mt][nt][3])
                    : "r"(af[mt][0]), "r"(af[mt][1]), "r"(af[mt][2]), "r"(af[mt][3]),
                      "r"(bf[nt][0]), "r"(bf[nt][1]));
            }

        if (kt + 1 < nk) {
            As[nxt][acol + 0][arow] = f2tf32(aReg.x);
            As[nxt][acol + 1][arow] = f2tf32(aReg.y);
            As[nxt][acol + 2][arow] = f2tf32(aReg.z);
            As[nxt][acol + 3][arow] = f2tf32(aReg.w);
            Bs[nxt][brow][bcol + 0] = f2tf32(bReg.x);
            Bs[nxt][brow][bcol + 1] = f2tf32(bReg.y);
            Bs[nxt][brow][bcol + 2] = f2tf32(bReg.z);
            Bs[nxt][brow][bcol + 3] = f2tf32(bReg.w);
        }
        __syncthreads();
    }

    #pragma unroll
    for (int mt = 0; mt < 4; mt++) {
        int r0 = bm + warp_m + mt * 16 + gid;
        #pragma unroll
        for (int nt = 0; nt < 4; nt++) {
            int c0 = bn + warp_n + nt * 8 + tg * 2;
            if (r0 < M)
                *(__half2*)&C[(size_t)r0 * N + c0] =
                    __floats2half2_rn(acc[mt][nt][0], acc[mt][nt][1]);
            if (r0 + 8 < M)
                *(__half2*)&C[(size_t)(r0 + 8) * N + c0] =
                    __floats2half2_rn(acc[mt][nt][2], acc[mt][nt][3]);
        }
    }
}

// ---------------- CSR gathers over fp16 rows (fp32 accumulate) ----------------
// LPG lanes per row-group; each lane handles 8 halves (uint4 = 16B). C = LPG*8.
template<int LPG, int RPB>
__global__ __launch_bounds__(LPG * RPB)
void k_gather_hh(const uint4* __restrict__ src,
                 const int* __restrict__ off,
                 const int* __restrict__ nbr,
                 const float* __restrict__ dscale,
                 uint4* __restrict__ dst, int nrows) {
    const int group = threadIdx.x / LPG;
    const int lane  = threadIdx.x % LPG;
    const int row = blockIdx.x * RPB + group;
    if (row >= nrows) return;
    const int s0 = off[row], s1 = off[row + 1];
    float2 acc[4] = {};
    int j = s0;
    for (; j + 1 < s1; j += 2) {
        int n0 = __ldg(&nbr[j]);
        int n1 = __ldg(&nbr[j + 1]);
        uint4 p = src[(size_t)n0 * LPG + lane];
        uint4 q = src[(size_t)n1 * LPG + lane];
        const __half2* ph = (const __half2*)&p;
        const __half2* qh = (const __half2*)&q;
        #pragma unroll
        for (int i = 0; i < 4; i++) {
            float2 a = __half22float2(ph[i]);
            float2 b = __half22float2(qh[i]);
            acc[i].x += a.x + b.x;
            acc[i].y += a.y + b.y;
        }
    }
    if (j < s1) {
        int n0 = __ldg(&nbr[j]);
        uint4 p = src[(size_t)n0 * LPG + lane];
        const __half2* ph = (const __half2*)&p;
        #pragma unroll
        for (int i = 0; i < 4; i++) {
            float2 a = __half22float2(ph[i]);
            acc[i].x += a.x;
            acc[i].y += a.y;
        }
    }
    float s = dscale[row];
    uint4 outw;
    __half2* oh = (__half2*)&outw;
    #pragma unroll
    for (int i = 0; i < 4; i++)
        oh[i] = __floats2half2_rn(acc[i].x * s, acc[i].y * s);
    dst[(size_t)row * LPG + lane] = outw;
}

template<int LPG, int RPB>
__global__ __launch_bounds__(LPG * RPB)
void k_gather_hf(const uint4* __restrict__ src,
                 const int* __restrict__ off,
                 const int* __restrict__ nbr,
                 const float* __restrict__ dscale,
                 const float* __restrict__ bias,
                 float4* __restrict__ dst, int nrows, int do_elu) {
    const int group = threadIdx.x / LPG;
    const int lane  = threadIdx.x % LPG;
    const int row = blockIdx.x * RPB + group;
    if (row >= nrows) return;
    const int s0 = off[row], s1 = off[row + 1];
    float2 acc[4] = {};
    int j = s0;
    for (; j + 1 < s1; j += 2) {
        int n0 = __ldg(&nbr[j]);
        int n1 = __ldg(&nbr[j + 1]);
        uint4 p = src[(size_t)n0 * LPG + lane];
        uint4 q = src[(size_t)n1 * LPG + lane];
        const __half2* ph = (const __half2*)&p;
        const __half2* qh = (const __half2*)&q;
        #pragma unroll
        for (int i = 0; i < 4; i++) {
            float2 a = __half22float2(ph[i]);
            float2 b = __half22float2(qh[i]);
            acc[i].x += a.x + b.x;
            acc[i].y += a.y + b.y;
        }
    }
    if (j < s1) {
        int n0 = __ldg(&nbr[j]);
        uint4 p = src[(size_t)n0 * LPG + lane];
        const __half2* ph = (const __half2*)&p;
        #pragma unroll
        for (int i = 0; i < 4; i++) {
            float2 a = __half22float2(ph[i]);
            acc[i].x += a.x;
            acc[i].y += a.y;
        }
    }
    float s = dscale[row];
    float v[8];
    #pragma unroll
    for (int i = 0; i < 4; i++) { v[2*i] = acc[i].x * s; v[2*i+1] = acc[i].y * s; }
    const float* bp = bias + lane * 8;
    #pragma unroll
    for (int i = 0; i < 8; i++) v[i] += bp[i];
    if (do_elu) {
        #pragma unroll
        for (int i = 0; i < 8; i++) v[i] = v[i] > 0.f ? v[i] : expm1f(v[i]);
    }
    float4* dp = dst + (size_t)row * (LPG * 2) + lane * 2;
    dp[0] = make_float4(v[0], v[1], v[2], v[3]);
    dp[1] = make_float4(v[4], v[5], v[6], v[7]);
}

// ---------------- host driver ----------------
static inline int cdiv(int a, int b) { return (a + b - 1) / b; }

extern "C" void kernel_launch(void* const* d_in, const int* in_sizes, int n_in,
                              void* d_out, int out_size) {
    const float* x  = (const float*)d_in[0];
    const void*  ei = d_in[1];
    const float* W1 = (const float*)d_in[3];
    const float* b1 = (const float*)d_in[4];
    const float* W2 = (const float*)d_in[5];
    const float* b2 = (const float*)d_in[6];
    const float* W3 = (const float*)d_in[7];
    const float* b3 = (const float*)d_in[8];

    float *A, *B, *C, *inv_v, *inv_e;
    int *cnt_v, *cnt_e, *cur_v, *cur_e;
    cudaGetSymbolAddress((void**)&A, g_bufA);
    cudaGetSymbolAddress((void**)&B, g_bufB);
    cudaGetSymbolAddress((void**)&C, g_bufC);
    cudaGetSymbolAddress((void**)&inv_v, g_inv_v);
    cudaGetSymbolAddress((void**)&inv_e, g_inv_e);
    cudaGetSymbolAddress((void**)&cnt_v, g_cnt_v);
    cudaGetSymbolAddress((void**)&cnt_e, g_cnt_e);
    cudaGetSymbolAddress((void**)&cur_v, g_cur_v);
    cudaGetSymbolAddress((void**)&cur_e, g_cur_e);
    int *off_v, *off_e, *nbr_v, *nbr_e;
    cudaGetSymbolAddress((void**)&off_v, g_off_v);
    cudaGetSymbolAddress((void**)&off_e, g_off_e);
    cudaGetSymbolAddress((void**)&nbr_v, g_nbr_v);
    cudaGetSymbolAddress((void**)&nbr_e, g_nbr_e);

    const int TB = 256;

    k_zero_i<<<cdiv(N_NODES, TB), TB>>>(cnt_v, N_NODES);
    k_zero_i<<<cdiv(N_HEDGES, TB), TB>>>(cnt_e, N_HEDGES);
    k_zero_i<<<cdiv(N_NODES, TB), TB>>>(cur_v, N_NODES);
    k_zero_i<<<cdiv(N_HEDGES, TB), TB>>>(cur_e, N_HEDGES);
    k_detect<<<1, 32>>>((const int*)ei);
    k_convert<<<cdiv(NNZ, TB), TB>>>(ei);
    k_scan<<<2, 1024>>>();
    k_fill<<<cdiv(NNZ, TB), TB>>>();
    k_invdeg<<<cdiv(N_NODES, TB), TB>>>();

    // layer: gemm(fp32 in -> fp16 msg) -> gather_hh (v->e, *inv_e) -> gather_hf (e->v, *inv_v+bias+ELU)
    auto layer = [&](const float* hin, const float* W, const float* bias,
                     float* hout, int Cin, int Cout, int elu) {
        __half* msg = (__half*)A;
        __half* xe  = (__half*)B;
        dim3 gg(Cout / 128, cdiv(N_NODES, 128));
        k_tgemm<<<gg, 256>>>(hin, W, msg, N_NODES, Cin, Cout);
        if (Cout == 256) {
            k_gather_hh<32, 8><<<cdiv(N_HEDGES, 8), 256>>>(
                (const uint4*)msg, off_e, nbr_e, inv_e, (uint4*)xe, N_HEDGES);
            k_gather_hf<32, 8><<<cdiv(N_NODES, 8), 256>>>(
                (const uint4*)xe, off_v, nbr_v, inv_v, bias,
                (float4*)hout, N_NODES, elu);
        } else {
            k_gather_hh<16, 16><<<cdiv(N_HEDGES, 16), 256>>>(
                (const uint4*)msg, off_e, nbr_e, inv_e, (uint4*)xe, N_HEDGES);
            k_gather_hf<16, 16><<<cdiv(N_NODES, 16), 256>>>(
                (const uint4*)xe, off_v, nbr_v, inv_v, bias,
                (float4*)hout, N_NODES, elu);
        }
    };

    float* out = (float*)d_out;

    layer(x, W1, b1, C, F_IN, HID, 1);
    layer(C, W2, b2, C, HID, HID, 1);
    layer(C, W3, b3, out, HID, F_OUT, 0);
}